// round 2
// baseline (speedup 1.0000x reference)
#include <cuda_runtime.h>
#include <cstddef>

// VarConvND: per-location (unshared) 3x3 conv as 4096 independent GEMMs.
//   X:      [B=64, C_IN=32, H=64, W=64] fp32
//   weight: [S=4096, K=288, C_OUT=16]   fp32
//   bias:   [H_OUT=64, W_OUT=64] -> [S] fp32
//   out:    [B=64, C_OUT=16, 64, 64]    fp32
//
// out[b,c,s] = sum_k (ufld[b,k,s] + bias[s]) * w[s,k,c]
//            = sum_k ufld[b,k,s]*w[s,k,c] + bias[s] * sum_k w[s,k,c]

#define S_TOT 4096
#define KK    288
#define K4N   72          // KK/4
#define CO    16
#define CI    32
#define BB    64
#define HH    64
#define WW    64
#define BT    16          // batch tile per compute pass

__global__ __launch_bounds__(256, 6)
void varconv_kernel(const float* __restrict__ X,
                    const float* __restrict__ Wg,
                    const float* __restrict__ bias,
                    float* __restrict__ out)
{
    // w4[k4][c]  : weight, k-chunks of 4 per float4, conflict-free per phase
    // u4[k4][b]  : unfold tile for BT batches, same layout
    __shared__ float4 w4[K4N][CO];
    __shared__ float4 u4[K4N][BT];
    __shared__ float  colsum[CO];

    const int s   = blockIdx.x;
    const int y   = s >> 6;
    const int x   = s & 63;
    const int tid = threadIdx.x;

    // ---- load weight tile [288,16] -> w4[k4][c] ----
    // global element g = k*16 + c  (c fastest), so a float4 covers (k, c..c+3)
    {
        const float4* wgl = (const float4*)(Wg + (size_t)s * (KK * CO));
        float* wsm = (float*)w4;
        #pragma unroll
        for (int i = tid; i < (KK * CO) / 4; i += 256) {
            float4 v = wgl[i];
            int g  = i << 2;
            int k  = g >> 4;
            int c  = g & 15;
            int k4 = k >> 2, kr = k & 3;
            int base = (k4 * CO + c) * 4 + kr;
            wsm[base]      = v.x;
            wsm[base + 4]  = v.y;
            wsm[base + 8]  = v.z;
            wsm[base + 12] = v.w;
        }
    }
    __syncthreads();

    // colsum[c] = sum_k w[k][c]   (for the folded bias term)
    if (tid < CO) {
        float sum = 0.f;
        #pragma unroll
        for (int k4 = 0; k4 < K4N; k4++) {
            float4 w = w4[k4][tid];
            sum += (w.x + w.y) + (w.z + w.w);
        }
        colsum[tid] = sum;
    }

    const int   c_out  = tid & 15;   // also lane16 for the load phase
    const int   bq     = tid >> 4;   // local batch index 0..15
    const float bval   = bias[s];
    float* usm = (float*)u4;

    for (int bt = 0; bt < BB / BT; bt++) {
        if (bt) __syncthreads();     // previous tile's readers done

        // ---- build unfold tile: u4[k4][bq] for batches bt*BT .. +15 ----
        {
            const int b = bt * BT + bq;
            const float* Xb = X + (size_t)b * (CI * HH * WW);
            for (int k = c_out; k < KK; k += 16) {
                int c  = k / 9;
                int r  = k - c * 9;
                int i3 = r / 3;
                int di = i3 - 1;
                int dj = (r - i3 * 3) - 1;
                int yy = y + di;
                int xx = x + dj;
                float v = 0.f;
                if ((unsigned)yy < HH && (unsigned)xx < WW)
                    v = Xb[(c * HH + yy) * WW + xx];
                usm[((k >> 2) * BT + bq) * 4 + (k & 3)] = v;
            }
        }
        __syncthreads();

        // ---- compute: thread (bq, c_out) does a 288-length dot ----
        float a0 = 0.f, a1 = 0.f, a2 = 0.f, a3 = 0.f;
        #pragma unroll
        for (int k4 = 0; k4 < K4N; k4++) {
            float4 u = u4[k4][bq];
            float4 w = w4[k4][c_out];
            a0 += u.x * w.x;
            a1 += u.y * w.y;
            a2 += u.z * w.z;
            a3 += u.w * w.w;
        }

        const int b = bt * BT + bq;
        out[(size_t)(b * CO + c_out) * S_TOT + s] =
            (a0 + a1) + (a2 + a3) + bval * colsum[c_out];
    }
}

extern "C" void kernel_launch(void* const* d_in, const int* in_sizes, int n_in,
                              void* d_out, int out_size)
{
    const float* X    = (const float*)d_in[0];
    const float* Wg   = (const float*)d_in[1];
    const float* bias = (const float*)d_in[2];
    float* out        = (float*)d_out;
    (void)in_sizes; (void)n_in; (void)out_size;

    varconv_kernel<<<S_TOT, 256>>>(X, Wg, bias, out);
}

// round 3
// speedup vs baseline: 3.4849x; 3.4849x over previous
#include <cuda_runtime.h>
#include <cstddef>
#include <cstdint>

// VarConvND: per-location (unshared) 3x3 conv = 4096 independent GEMMs
//   [B=64 x K=288] x [K=288 x C_OUT=16], fp32 in/out, tf32 tensor-core compute.
//
// out[b,c,s] = sum_k (patch[b,k,s] + bias[s]) * w[s,k,c]
// (bias added to every unfolded element, including zero-padded borders,
//  exactly like the reference.)

#define S_TOT 4096
#define KK    288
#define CO    16
#define CI    32
#define BB    64
#define HH    64
#define WW    64
#define NK8   36      // KK / 8
#define P_TOT (CI*HH*WW)   // 131072

// Scratch: X transposed to [p][b] so batch is contiguous (coalesced patch loads).
__device__ float g_Xt[(size_t)P_TOT * BB];

// ---------------- transpose X[b][p] -> Xt[p][b] ----------------
__global__ void transpose_kernel(const float* __restrict__ X, float* __restrict__ Xt)
{
    __shared__ float t[32][33];
    const int tx = threadIdx.x, ty = threadIdx.y;
    const int p0 = blockIdx.x * 32, b0 = blockIdx.y * 32;
    #pragma unroll
    for (int i = 0; i < 32; i += 8)
        t[ty + i][tx] = X[(size_t)(b0 + ty + i) * P_TOT + p0 + tx];
    __syncthreads();
    #pragma unroll
    for (int i = 0; i < 32; i += 8)
        Xt[(size_t)(p0 + ty + i) * BB + b0 + tx] = t[tx][ty + i];
}

// ---------------- main tf32 MMA kernel ----------------
__device__ __forceinline__ unsigned f2tf(float f)
{
    unsigned u;
    asm("cvt.rna.tf32.f32 %0, %1;" : "=r"(u) : "f"(f));
    return u;
}

__global__ __launch_bounds__(128)
void varconv_mma(const float* __restrict__ Wg,
                 const float* __restrict__ bias,
                 float* __restrict__ out)
{
    // Weight in tf32 B-fragment layout: wf[ks][nt][lane][r]
    //   value(k, c): ks=k>>3, r=(k>>2)&1, nt=c>>3, lane=((c&7)<<2)|(k&3)
    __shared__ unsigned wf[NK8 * 2 * 32 * 2];   // 18432 B

    const int s    = blockIdx.x;
    const int y    = s >> 6;
    const int x    = s & 63;
    const int tid  = threadIdx.x;
    const int lane = tid & 31;
    const int wid  = tid >> 5;        // warp = m-tile (0..3)
    const float bval = bias[s];

    // ---- load + convert weight tile [288 x 16] into fragment layout ----
    {
        const float4* wg = (const float4*)(Wg + (size_t)s * (KK * CO));
        #pragma unroll
        for (int i = tid; i < (KK * CO) / 4; i += 128) {
            float4 v = wg[i];
            int g  = i << 2;         // element index, c fastest
            int k  = g >> 4;
            int cb = g & 15;         // c = cb..cb+3
            int ks = k >> 3;
            int r  = (k >> 2) & 1;
            int kl = k & 3;
            float vv[4] = {v.x, v.y, v.z, v.w};
            #pragma unroll
            for (int j = 0; j < 4; j++) {
                int c  = cb + j;
                int nt = c >> 3;
                int l  = ((c & 7) << 2) | kl;
                wf[((ks * 2 + nt) * 32 + l) * 2 + r] = f2tf(vv[j]);
            }
        }
    }
    __syncthreads();

    // Thread's fixed role in its warp's A fragments:
    //   a0=(row,col) a1=(row+8,col) a2=(row,col+4) a3=(row+8,col+4)
    //   row = lane>>2, col = lane&3  ->  batch b0 = wid*16 + row
    const int rowlow = lane >> 2;
    const int cc     = lane & 3;
    const int b0     = wid * 16 + rowlow;

    float acc[2][4] = {};

    #pragma unroll 4
    for (int ks = 0; ks < NK8; ks++) {
        const int kA = ks * 8 + cc;     // col cc
        const int kB = kA + 4;          // col cc+4

        float vA0 = bval, vA1 = bval, vB0 = bval, vB1 = bval;
        {
            int cin = kA / 9;
            int tap = kA - cin * 9;
            int t3  = tap / 3;
            int yy  = y + t3 - 1;
            int xx  = x + (tap - t3 * 3) - 1;
            if (((unsigned)yy < (unsigned)HH) & ((unsigned)xx < (unsigned)WW)) {
                const float* p = g_Xt + ((size_t)((cin << 12) + (yy << 6) + xx) << 6);
                vA0 += p[b0];
                vA1 += p[b0 + 8];
            }
        }
        {
            int cin = kB / 9;
            int tap = kB - cin * 9;
            int t3  = tap / 3;
            int yy  = y + t3 - 1;
            int xx  = x + (tap - t3 * 3) - 1;
            if (((unsigned)yy < (unsigned)HH) & ((unsigned)xx < (unsigned)WW)) {
                const float* p = g_Xt + ((size_t)((cin << 12) + (yy << 6) + xx) << 6);
                vB0 += p[b0];
                vB1 += p[b0 + 8];
            }
        }

        const unsigned a0 = f2tf(vA0);
        const unsigned a1 = f2tf(vA1);
        const unsigned a2 = f2tf(vB0);
        const unsigned a3 = f2tf(vB1);

        #pragma unroll
        for (int nt = 0; nt < 2; nt++) {
            uint2 bfr = *(const uint2*)&wf[((ks * 2 + nt) * 32 + lane) * 2];
            asm volatile(
                "mma.sync.aligned.m16n8k8.row.col.f32.tf32.tf32.f32 "
                "{%0,%1,%2,%3}, {%4,%5,%6,%7}, {%8,%9}, {%0,%1,%2,%3};"
                : "+f"(acc[nt][0]), "+f"(acc[nt][1]),
                  "+f"(acc[nt][2]), "+f"(acc[nt][3])
                : "r"(a0), "r"(a1), "r"(a2), "r"(a3),
                  "r"(bfr.x), "r"(bfr.y));
        }
    }

    // ---- epilogue: D fragment c0=(row,col) c1=(row,col+1) c2=(row+8,col) c3=(row+8,col+1)
    const int drow = lane >> 2;
    const int dcol = (lane & 3) * 2;
    #pragma unroll
    for (int nt = 0; nt < 2; nt++) {
        #pragma unroll
        for (int j = 0; j < 4; j++) {
            int c = nt * 8 + dcol + (j & 1);
            int b = wid * 16 + drow + (j >> 1) * 8;
            out[(size_t)(b * CO + c) * S_TOT + s] = acc[nt][j];
        }
    }
}

extern "C" void kernel_launch(void* const* d_in, const int* in_sizes, int n_in,
                              void* d_out, int out_size)
{
    const float* X    = (const float*)d_in[0];
    const float* Wg   = (const float*)d_in[1];
    const float* bias = (const float*)d_in[2];
    float* out        = (float*)d_out;
    (void)in_sizes; (void)n_in; (void)out_size;

    float* Xt = nullptr;
    cudaGetSymbolAddress((void**)&Xt, g_Xt);

    dim3 tb(32, 8);
    dim3 tg(P_TOT / 32, BB / 32);
    transpose_kernel<<<tg, tb>>>(X, Xt);

    varconv_mma<<<S_TOT, 128>>>(Wg, bias, out);
}

// round 7
// speedup vs baseline: 3.7680x; 1.0812x over previous
#include <cuda_runtime.h>
#include <cstddef>
#include <cstdint>

// VarConvND: per-location (unshared) 3x3 conv = 4096 independent GEMMs
//   [B=64 x K=288] x [K=288 x C_OUT=16], tf32 tensor cores, smem-staged A.
//
// out[b,c,s] = sum_k (patch[b,k,s] + bias[s]) * w[s,k,c]

#define S_TOT 4096
#define KK    288
#define CO    16
#define CI    32
#define BB    64
#define HH    64
#define WW    64
#define NK8   36                 // KK / 8
#define P_TOT (CI*HH*WW)         // 131072
#define CK    72                 // k-rows per chunk (4 chunks)
#define AST   72                 // smA row stride in words (bank-conflict-free)

// Scratch: X transposed to [p][b] so batch is contiguous (coalesced loads).
__device__ float g_Xt[(size_t)P_TOT * BB];

// ---------------- transpose X[b][p] -> Xt[p][b] ----------------
__global__ void transpose_kernel(const float* __restrict__ X, float* __restrict__ Xt)
{
    __shared__ float t[32][33];
    const int tx = threadIdx.x, ty = threadIdx.y;
    const int p0 = blockIdx.x * 32, b0 = blockIdx.y * 32;
    #pragma unroll
    for (int i = 0; i < 32; i += 8)
        t[ty + i][tx] = X[(size_t)(b0 + ty + i) * P_TOT + p0 + tx];
    __syncthreads();
    #pragma unroll
    for (int i = 0; i < 32; i += 8)
        Xt[(size_t)(p0 + ty + i) * BB + b0 + tx] = t[tx][ty + i];
}

__device__ __forceinline__ unsigned f2tf(float f)
{
    unsigned u;
    asm("cvt.rna.tf32.f32 %0, %1;" : "=r"(u) : "f"(f));
    return u;
}

__global__ __launch_bounds__(128)
void varconv_mma(const float* __restrict__ Wg,
                 const float* __restrict__ bias,
                 float* __restrict__ out)
{
    // Weight in tf32 B-fragment layout: wf[ks][nt][lane][r]
    __shared__ unsigned wf[NK8 * 2 * 32 * 2];   // 18432 B
    // A chunk: 72 k-rows x 64 batches (tf32, bias folded), stride 72 words
    __shared__ unsigned smA[CK * AST];          // 20736 B

    const int s    = blockIdx.x;
    const int y    = s >> 6;
    const int x    = s & 63;
    const int tid  = threadIdx.x;
    const int lane = tid & 31;
    const int wid  = tid >> 5;
    const float bval = bias[s];

    // ---- load + convert weight tile [288 x 16] into fragment layout ----
    {
        const float4* wg = (const float4*)(Wg + (size_t)s * (KK * CO));
        #pragma unroll
        for (int i = tid; i < (KK * CO) / 4; i += 128) {
            float4 v = wg[i];
            int g  = i << 2;
            int k  = g >> 4;
            int cb = g & 15;
            int ks = k >> 3;
            int r  = (k >> 2) & 1;
            int kl = k & 3;
            float vv[4] = {v.x, v.y, v.z, v.w};
            #pragma unroll
            for (int j = 0; j < 4; j++) {
                int c  = cb + j;
                int nt = c >> 3;
                int l  = ((c & 7) << 2) | kl;
                wf[((ks * 2 + nt) * 32 + l) * 2 + r] = f2tf(vv[j]);
            }
        }
    }

    // ---- staging roles: thread loads float4 of batches f4*4, rows rhi+8*it ----
    const int rhi = tid >> 4;     // 0..7
    const int f4  = tid & 15;     // which float4 of the 64 batches

    float4 pf[9];

    auto prefetch = [&](int chunk) {
        #pragma unroll
        for (int it = 0; it < 9; it++) {
            int row = it * 8 + rhi;            // 0..71
            int cl  = row / 9;
            int tap = row - cl * 9;
            int cin = chunk * 8 + cl;
            int t3  = tap / 3;
            int yy  = y + t3 - 1;
            int xx  = x + (tap - t3 * 3) - 1;
            float4 v = make_float4(0.f, 0.f, 0.f, 0.f);
            if (((unsigned)yy < (unsigned)HH) & ((unsigned)xx < (unsigned)WW))
                v = *(const float4*)(g_Xt +
                        ((size_t)((cin << 12) + (yy << 6) + xx) << 6) + f4 * 4);
            pf[it] = v;
        }
    };
    auto store_pf = [&]() {
        #pragma unroll
        for (int it = 0; it < 9; it++) {
            int row = it * 8 + rhi;
            uint4 u;
            u.x = f2tf(pf[it].x + bval);
            u.y = f2tf(pf[it].y + bval);
            u.z = f2tf(pf[it].z + bval);
            u.w = f2tf(pf[it].w + bval);
            *(uint4*)&smA[row * AST + f4 * 4] = u;
        }
    };

    prefetch(0);
    __syncthreads();          // wf visible
    store_pf();
    __syncthreads();          // smA chunk 0 visible

    const int cc = lane & 3;
    const int b0 = wid * 16 + (lane >> 2);
    float acc[2][4] = {};

    for (int chunk = 0; chunk < 4; chunk++) {
        if (chunk < 3) prefetch(chunk + 1);   // LDG issued before compute

        #pragma unroll
        for (int ks = 0; ks < 9; ks++) {
            const int kc  = ks * 8 + cc;
            const unsigned a0 = smA[kc * AST + b0];
            const unsigned a1 = smA[kc * AST + b0 + 8];
            const unsigned a2 = smA[(kc + 4) * AST + b0];
            const unsigned a3 = smA[(kc + 4) * AST + b0 + 8];
            const int ksg = chunk * 9 + ks;
            #pragma unroll
            for (int nt = 0; nt < 2; nt++) {
                uint2 bfr = *(const uint2*)&wf[((ksg * 2 + nt) * 32 + lane) * 2];
                asm volatile(
                    "mma.sync.aligned.m16n8k8.row.col.f32.tf32.tf32.f32 "
                    "{%0,%1,%2,%3}, {%4,%5,%6,%7}, {%8,%9}, {%0,%1,%2,%3};"
                    : "+f"(acc[nt][0]), "+f"(acc[nt][1]),
                      "+f"(acc[nt][2]), "+f"(acc[nt][3])
                    : "r"(a0), "r"(a1), "r"(a2), "r"(a3),
                      "r"(bfr.x), "r"(bfr.y));
            }
        }

        __syncthreads();                       // compute readers done
        if (chunk < 3) {
            store_pf();
            __syncthreads();                   // next chunk visible
        }
    }

    // ---- epilogue: D fragment c0=(row,col) c1=(row,col+1) c2=(row+8,col) c3=(row+8,col+1)
    const int drow = lane >> 2;
    const int dcol = (lane & 3) * 2;
    #pragma unroll
    for (int nt = 0; nt < 2; nt++) {
        #pragma unroll
        for (int j = 0; j < 4; j++) {
            int c = nt * 8 + dcol + (j & 1);
            int b = wid * 16 + drow + (j >> 1) * 8;
            out[(size_t)(b * CO + c) * S_TOT + s] = acc[nt][j];
        }
    }
}

extern "C" void kernel_launch(void* const* d_in, const int* in_sizes, int n_in,
                              void* d_out, int out_size)
{
    const float* X    = (const float*)d_in[0];
    const float* Wg   = (const float*)d_in[1];
    const float* bias = (const float*)d_in[2];
    float* out        = (float*)d_out;
    (void)in_sizes; (void)n_in; (void)out_size;

    float* Xt = nullptr;
    cudaGetSymbolAddress((void**)&Xt, g_Xt);

    dim3 tb(32, 8);
    dim3 tg(P_TOT / 32, BB / 32);
    transpose_kernel<<<tg, tb>>>(X, Xt);

    varconv_mma<<<S_TOT, 128>>>(Wg, bias, out);
}